// round 1
// baseline (speedup 1.0000x reference)
#include <cuda_runtime.h>
#include <math.h>

// Problem constants
#define HH    16
#define WW    16
#define DD    6
#define EMBD  32
#define CELLD 128
#define BB    32
#define NN    8
#define BND   256           // B*N
#define QQ    1536          // D*H*W
#define KKEY  256           // H*W
#define TQ    64            // q rows per block

// ---- scratch (device globals; no allocations allowed) ----
__device__ float g_pose_trans[BND * 12];
__device__ float g_embo[KKEY * EMBD];

__device__ __forceinline__ float lin16(int i) { return -1.0f + (2.0f / 15.0f) * (float)i; }

__device__ __forceinline__ void mat2quat7(const float* m, float* out7) {
    float m00 = m[0], m01 = m[1], m02 = m[2], tx = m[3];
    float m10 = m[4], m11 = m[5], m12 = m[6], ty = m[7];
    float m20 = m[8], m21 = m[9], m22 = m[10], tz = m[11];
    float t, q0, q1, q2, q3;
    if (m22 < 0.0f) {
        if (m00 > m11) {
            t = 1.0f + m00 - m11 - m22;
            q0 = t; q1 = m01 + m10; q2 = m20 + m02; q3 = m12 - m21;
        } else {
            t = 1.0f - m00 + m11 - m22;
            q0 = m01 + m10; q1 = t; q2 = m12 + m21; q3 = m20 - m02;
        }
    } else {
        if (m00 < -m11) {
            t = 1.0f - m00 - m11 + m22;
            q0 = m20 + m02; q1 = m12 + m21; q2 = t; q3 = m01 - m10;
        } else {
            t = 1.0f + m00 + m11 + m22;
            q0 = m12 - m21; q1 = m20 - m02; q2 = m01 - m10; q3 = t;
        }
    }
    float s = 0.5f / sqrtf(t);
    out7[0] = tx; out7[1] = ty; out7[2] = tz;
    out7[3] = q0 * s; out7[4] = q1 * s; out7[5] = q2 * s; out7[6] = q3 * s;
}

// =================== Kernel A: poses + key embeddings ===================
__global__ void kA(const float* __restrict__ pose_o, const float* __restrict__ pose_q,
                   const float* __restrict__ Wk1, const float* __restrict__ bk1,
                   const float* __restrict__ Wk2, const float* __restrict__ bk2,
                   float* __restrict__ out_poq, float* __restrict__ out_pqq)
{
    int t = threadIdx.x;  // 256 threads, 1 block

    // pose_o quats
    {
        float q7[7];
        mat2quat7(pose_o + t * 12, q7);
#pragma unroll
        for (int i = 0; i < 7; i++) out_poq[t * 7 + i] = q7[i];
    }
    // pose_q quats
    if (t < BB) {
        float q7[7];
        mat2quat7(pose_q + t * 12, q7);
#pragma unroll
        for (int i = 0; i < 7; i++) out_pqq[t * 7 + i] = q7[i];
    }

    // relative pose: inv([Ro|to]) @ [Rq|tq]  (fp64 adjugate inverse)
    {
        const float* po = pose_o + t * 12;
        const float* pq = pose_q + (t >> 3) * 12;
        double a[3][3], to[3], Rq[3][3], tq[3];
#pragma unroll
        for (int i = 0; i < 3; i++) {
#pragma unroll
            for (int j = 0; j < 3; j++) { a[i][j] = po[i * 4 + j]; Rq[i][j] = pq[i * 4 + j]; }
            to[i] = po[i * 4 + 3]; tq[i] = pq[i * 4 + 3];
        }
        double c00 = a[1][1] * a[2][2] - a[1][2] * a[2][1];
        double c01 = a[1][2] * a[2][0] - a[1][0] * a[2][2];
        double c02 = a[1][0] * a[2][1] - a[1][1] * a[2][0];
        double det = a[0][0] * c00 + a[0][1] * c01 + a[0][2] * c02;
        double inv[3][3];
        inv[0][0] = c00 / det;
        inv[1][0] = c01 / det;
        inv[2][0] = c02 / det;
        inv[0][1] = (a[0][2] * a[2][1] - a[0][1] * a[2][2]) / det;
        inv[1][1] = (a[0][0] * a[2][2] - a[0][2] * a[2][0]) / det;
        inv[2][1] = (a[0][1] * a[2][0] - a[0][0] * a[2][1]) / det;
        inv[0][2] = (a[0][1] * a[1][2] - a[0][2] * a[1][1]) / det;
        inv[1][2] = (a[0][2] * a[1][0] - a[0][0] * a[1][2]) / det;
        inv[2][2] = (a[0][0] * a[1][1] - a[0][1] * a[1][0]) / det;
#pragma unroll
        for (int i = 0; i < 3; i++) {
#pragma unroll
            for (int j = 0; j < 3; j++) {
                double s = 0.0;
#pragma unroll
                for (int k = 0; k < 3; k++) s += inv[i][k] * Rq[k][j];
                g_pose_trans[t * 12 + i * 4 + j] = (float)s;
            }
            double s = 0.0;
#pragma unroll
            for (int k = 0; k < 3; k++) s += inv[i][k] * (tq[k] - to[k]);
            g_pose_trans[t * 12 + i * 4 + 3] = (float)s;
        }
    }

    // key embeddings: 2 -> 128 relu -> 32, one key per thread
    {
        float c0 = lin16(t >> 4), c1 = lin16(t & 15);
        float h[128];
#pragma unroll
        for (int j = 0; j < 128; j++) {
            float v = fmaf(c0, Wk1[j], fmaf(c1, Wk1[128 + j], bk1[j]));
            h[j] = fmaxf(v, 0.0f);
        }
#pragma unroll 4
        for (int e = 0; e < EMBD; e++) {
            float s = bk2[e];
#pragma unroll
            for (int j = 0; j < 128; j++) s = fmaf(h[j], Wk2[j * EMBD + e], s);
            g_embo[t * EMBD + e] = s;
        }
    }
}

// =================== Kernel B: fused main ===================
// smem layout (float offsets)
#define OFF_WQ2T  0                         // [32][258]
#define OFF_BQ2   (OFF_WQ2T + 32*258)       // [32]
#define OFF_WA1T  (OFF_BQ2 + 32)            // [64][33]
#define OFF_WA2   (OFF_WA1T + 64*33)        // [64]
#define OFF_BA1   (OFF_WA2 + 64)            // [64]
#define OFF_EMBO  (OFF_BA1 + 64)            // [256][33]
#define OFF_EMBQ  (OFF_EMBO + 256*33)       // [64][33]
#define OFF_HID   (OFF_EMBQ + 64*33)        // [64][258]  (union: att)
#define OFF_V     (OFF_HID + 64*258)        // [128][66]  (union: a1[64][65], out-staging)
#define OFF_MASKW (OFF_V + 128*66)          // [64]
#define OFF_POSE  (OFF_MASKW + 64)          // [16]
#define OFF_CODE  (OFF_POSE + 16)           // [64][3]
#define SMEM_FLOATS (OFF_CODE + 64*3)
#define SMEM_BYTES  (SMEM_FLOATS * 4)

extern __shared__ float sm[];

__global__ void __launch_bounds__(256, 1)
kB(const float* __restrict__ vc,
   const float* __restrict__ Wq1, const float* __restrict__ bq1,
   const float* __restrict__ Wq2, const float* __restrict__ bq2,
   const float* __restrict__ Wa1, const float* __restrict__ ba1,
   const float* __restrict__ Wa2, const float* __restrict__ ba2,
   float* __restrict__ dout)
{
    const int t  = threadIdx.x;
    const int tx = t & 15;
    const int ty = t >> 4;
    const int qt = blockIdx.x;   // 0..23
    const int b  = blockIdx.y;   // 0..31

    float* sWq2T = sm + OFF_WQ2T;
    float* sbq2  = sm + OFF_BQ2;
    float* sWa1T = sm + OFF_WA1T;
    float* sWa2  = sm + OFF_WA2;
    float* sba1  = sm + OFF_BA1;
    float* sEmbO = sm + OFF_EMBO;
    float* sEmbQ = sm + OFF_EMBQ;
    float* sHid  = sm + OFF_HID;
    float* sAtt  = sm + OFF_HID;   // union
    float* sV    = sm + OFF_V;
    float* sA1   = sm + OFF_V;     // union
    float* sMW   = sm + OFF_MASKW;
    float* sPose = sm + OFF_POSE;
    float* sCode = sm + OFF_CODE;

    // ---- one-time loads ----
    for (int i = t; i < 256 * 32; i += 256) {
        int h = i >> 5, e = i & 31;
        sWq2T[e * 258 + h] = Wq2[i];
    }
    for (int i = t; i < 32 * 64; i += 256) {
        int e = i >> 6, j = i & 63;
        sWa1T[j * 33 + e] = Wa1[i];
    }
    if (t < 64) { sWa2[t] = Wa2[t]; sba1[t] = ba1[t]; }
    if (t < 32) sbq2[t] = bq2[t];
    for (int i = t; i < 256 * 32; i += 256) {
        int k = i >> 5, e = i & 31;
        sEmbO[k * 33 + e] = g_embo[i];
    }
    if (t < 64) {
        int q = qt * TQ + t;
        int d = q >> 8, rm = q & 255;
        sCode[t * 3 + 0] = 0.2f * (float)d;
        sCode[t * 3 + 1] = lin16(rm >> 4);
        sCode[t * 3 + 2] = lin16(rm & 15);
    }

    // per-thread hidden-layer weights (column t of Wq1) stay in registers
    float wq[15];
#pragma unroll
    for (int i = 0; i < 15; i++) wq[i] = Wq1[i * 256 + t];
    const float wb = bq1[t];
    const float ba2v = ba2[0];

    float acc[4][8];
#pragma unroll
    for (int i = 0; i < 4; i++)
#pragma unroll
        for (int j = 0; j < 8; j++) acc[i][j] = 0.0f;

    __syncthreads();

    for (int n = 0; n < NN; n++) {
        const int bn = b * NN + n;
        if (t < 12) sPose[t] = g_pose_trans[bn * 12 + t];
        __syncthreads();

        // ---- stage 1: hidden[64][256] = relu(inp @ Wq1 + b) ----
        {
            float base = wb;
#pragma unroll
            for (int i = 0; i < 12; i++) base = fmaf(sPose[i], wq[i], base);
#pragma unroll 4
            for (int r = 0; r < 64; r++) {
                float v = base;
                v = fmaf(sCode[r * 3 + 0], wq[12], v);
                v = fmaf(sCode[r * 3 + 1], wq[13], v);
                v = fmaf(sCode[r * 3 + 2], wq[14], v);
                sHid[r * 258 + t] = fmaxf(v, 0.0f);
            }
        }
        __syncthreads();

        // ---- stage 2: embq[64][32] = hidden @ Wq2 + b ----
        {
            const int rp = t >> 3;          // 0..31 -> rows rp*2, rp*2+1
            const int e4 = (t & 7) * 4;     // 4 consecutive emb cols
            float a0[4] = {0, 0, 0, 0}, a1[4] = {0, 0, 0, 0};
            const float* h0p = &sHid[(rp * 2) * 258];
            const float* h1p = &sHid[(rp * 2 + 1) * 258];
#pragma unroll 8
            for (int h = 0; h < 256; h += 2) {
                float2 h0 = *(const float2*)(h0p + h);
                float2 h1 = *(const float2*)(h1p + h);
#pragma unroll
                for (int j = 0; j < 4; j++) {
                    float2 w2 = *(const float2*)&sWq2T[(e4 + j) * 258 + h];
                    a0[j] = fmaf(h0.x, w2.x, a0[j]); a0[j] = fmaf(h0.y, w2.y, a0[j]);
                    a1[j] = fmaf(h1.x, w2.x, a1[j]); a1[j] = fmaf(h1.y, w2.y, a1[j]);
                }
            }
#pragma unroll
            for (int j = 0; j < 4; j++) {
                sEmbQ[(rp * 2) * 33 + e4 + j]     = a0[j] + sbq2[e4 + j];
                sEmbQ[(rp * 2 + 1) * 33 + e4 + j] = a1[j] + sbq2[e4 + j];
            }
        }
        __syncthreads();

        // ---- stage 3a: a1[64][64] = relu(embq @ Wa1 + ba1) ----
        {
            float mA[4][4];
#pragma unroll
            for (int i = 0; i < 4; i++)
#pragma unroll
                for (int j = 0; j < 4; j++) mA[i][j] = 0.0f;
#pragma unroll 4
            for (int e = 0; e < 32; e++) {
                float eq[4], wa[4];
#pragma unroll
                for (int i = 0; i < 4; i++) eq[i] = sEmbQ[(ty + 16 * i) * 33 + e];
#pragma unroll
                for (int j = 0; j < 4; j++) wa[j] = sWa1T[(tx + 16 * j) * 33 + e];
#pragma unroll
                for (int i = 0; i < 4; i++)
#pragma unroll
                    for (int j = 0; j < 4; j++) mA[i][j] = fmaf(eq[i], wa[j], mA[i][j]);
            }
#pragma unroll
            for (int i = 0; i < 4; i++)
#pragma unroll
                for (int j = 0; j < 4; j++)
                    sA1[(ty + 16 * i) * 65 + tx + 16 * j] =
                        fmaxf(mA[i][j] + sba1[tx + 16 * j], 0.0f);
        }
        __syncthreads();

        // ---- stage 3b: mask[r] = sigmoid(a1 @ Wa2 + ba2) ----
        if (t < 64) {
            float s = ba2v;
#pragma unroll 8
            for (int j = 0; j < 64; j++) s = fmaf(sA1[t * 65 + j], sWa2[j], s);
            sMW[t] = 1.0f / (1.0f + __expf(-s));
        }

        // ---- stage 4: logits[64][256] = embq @ emboT ----
#pragma unroll
        for (int p = 0; p < 2; p++) {
            float lg[4][8];
#pragma unroll
            for (int i = 0; i < 4; i++)
#pragma unroll
                for (int j = 0; j < 8; j++) lg[i][j] = 0.0f;
#pragma unroll 4
            for (int e = 0; e < 32; e++) {
                float eq[4], eo[8];
#pragma unroll
                for (int i = 0; i < 4; i++) eq[i] = sEmbQ[(ty + 16 * i) * 33 + e];
#pragma unroll
                for (int j = 0; j < 8; j++) eo[j] = sEmbO[(tx + 16 * j + 128 * p) * 33 + e];
#pragma unroll
                for (int i = 0; i < 4; i++)
#pragma unroll
                    for (int j = 0; j < 8; j++) lg[i][j] = fmaf(eq[i], eo[j], lg[i][j]);
            }
#pragma unroll
            for (int i = 0; i < 4; i++)
#pragma unroll
                for (int j = 0; j < 8; j++)
                    sAtt[(ty + 16 * i) * 258 + tx + 16 * j + 128 * p] = lg[i][j];
        }
        __syncthreads();

        // ---- stage 5: softmax rows; fold (mask/sum) into att ----
        {
            const int wid = t >> 5, lane = t & 31;
#pragma unroll
            for (int rr = 0; rr < 8; rr++) {
                const int r = wid * 8 + rr;
                float* row = &sAtt[r * 258];
                float mx = -1e30f;
#pragma unroll
                for (int k = lane; k < 256; k += 32) mx = fmaxf(mx, row[k]);
#pragma unroll
                for (int o = 16; o > 0; o >>= 1) mx = fmaxf(mx, __shfl_xor_sync(0xffffffffu, mx, o));
                float s = 0.0f;
#pragma unroll
                for (int k = lane; k < 256; k += 32) {
                    float e = __expf(row[k] - mx);
                    row[k] = e;
                    s += e;
                }
#pragma unroll
                for (int o = 16; o > 0; o >>= 1) s += __shfl_xor_sync(0xffffffffu, s, o);
                float wr = sMW[r] / s;
#pragma unroll
                for (int k = lane; k < 256; k += 32) row[k] *= wr;
            }
        }
        __syncthreads();

        // ---- stage 6: acc += att_weighted @ V^T (chunked over k) ----
        const float* vcn = vc + (size_t)bn * CELLD * KKEY;
        for (int kc = 0; kc < 4; kc++) {
            // stage V tile [128 c][64 k]
            for (int id = t; id < 2048; id += 256) {
                int c = id >> 4, f4 = id & 15;
                float4 vv = *(const float4*)(vcn + c * 256 + kc * 64 + f4 * 4);
                float* dst = &sV[c * 66 + f4 * 4];
                *(float2*)(dst)     = make_float2(vv.x, vv.y);
                *(float2*)(dst + 2) = make_float2(vv.z, vv.w);
            }
            __syncthreads();
            const int kb = kc * 64;
#pragma unroll 4
            for (int k = 0; k < 64; k += 2) {
                float2 a2[4], v2[8];
#pragma unroll
                for (int i = 0; i < 4; i++)
                    a2[i] = *(const float2*)&sAtt[(ty + 16 * i) * 258 + kb + k];
#pragma unroll
                for (int j = 0; j < 8; j++)
                    v2[j] = *(const float2*)&sV[(tx + 16 * j) * 66 + k];
#pragma unroll
                for (int i = 0; i < 4; i++)
#pragma unroll
                    for (int j = 0; j < 8; j++) {
                        acc[i][j] = fmaf(a2[i].x, v2[j].x, acc[i][j]);
                        acc[i][j] = fmaf(a2[i].y, v2[j].y, acc[i][j]);
                    }
            }
            __syncthreads();
        }
    } // n loop

    // ---- epilogue: sigmoid, transpose via smem, coalesced store ----
#pragma unroll
    for (int i = 0; i < 4; i++)
#pragma unroll
        for (int j = 0; j < 8; j++)
            sV[(tx + 16 * j) * 66 + ty + 16 * i] = 1.0f / (1.0f + __expf(-acc[i][j]));
    __syncthreads();

    float* outp = dout + (size_t)b * CELLD * QQ + qt * TQ;
    for (int id = t; id < CELLD * TQ; id += 256) {
        int c = id >> 6, r = id & 63;
        outp[(size_t)c * QQ + r] = sV[c * 66 + r];
    }
}

// =================== launch ===================
extern "C" void kernel_launch(void* const* d_in, const int* in_sizes, int n_in,
                              void* d_out, int out_size)
{
    (void)in_sizes; (void)n_in; (void)out_size;
    const float* view_cell = (const float*)d_in[0];
    const float* pose_o    = (const float*)d_in[1];
    const float* pose_q    = (const float*)d_in[2];
    const float* Wk1 = (const float*)d_in[3];
    const float* bk1 = (const float*)d_in[4];
    const float* Wk2 = (const float*)d_in[5];
    const float* bk2 = (const float*)d_in[6];
    const float* Wq1 = (const float*)d_in[7];
    const float* bq1 = (const float*)d_in[8];
    const float* Wq2 = (const float*)d_in[9];
    const float* bq2 = (const float*)d_in[10];
    const float* Wa1 = (const float*)d_in[11];
    const float* ba1 = (const float*)d_in[12];
    const float* Wa2 = (const float*)d_in[13];
    const float* ba2 = (const float*)d_in[14];

    float* out = (float*)d_out;
    float* out_poq = out + (size_t)BB * CELLD * QQ;           // [32,8,7]
    float* out_pqq = out_poq + (size_t)BB * NN * 7;           // [32,1,7]

    cudaFuncSetAttribute(kB, cudaFuncAttributeMaxDynamicSharedMemorySize, SMEM_BYTES);

    kA<<<1, 256>>>(pose_o, pose_q, Wk1, bk1, Wk2, bk2, out_poq, out_pqq);
    kB<<<dim3(24, 32), 256, SMEM_BYTES>>>(view_cell, Wq1, bq1, Wq2, bq2,
                                          Wa1, ba1, Wa2, ba2, out);
}

// round 2
// speedup vs baseline: 1.0594x; 1.0594x over previous
#include <cuda_runtime.h>
#include <math.h>

// Problem constants
#define HH    16
#define WW    16
#define DD    6
#define EMBD  32
#define CELLD 128
#define BB    32
#define NN    8
#define BND   256           // B*N
#define QQ    1536          // D*H*W
#define KKEY  256           // H*W
#define TQ    64            // q rows per block

// ---- scratch (device globals; no allocations allowed) ----
__device__ float g_pose_trans[BND * 12];
__device__ float g_embo[KKEY * EMBD];

__device__ __forceinline__ float lin16(int i) { return -1.0f + (2.0f / 15.0f) * (float)i; }

__device__ __forceinline__ void mat2quat7(const float* m, float* out7) {
    float m00 = m[0], m01 = m[1], m02 = m[2], tx = m[3];
    float m10 = m[4], m11 = m[5], m12 = m[6], ty = m[7];
    float m20 = m[8], m21 = m[9], m22 = m[10], tz = m[11];
    float t, q0, q1, q2, q3;
    if (m22 < 0.0f) {
        if (m00 > m11) {
            t = 1.0f + m00 - m11 - m22;
            q0 = t; q1 = m01 + m10; q2 = m20 + m02; q3 = m12 - m21;
        } else {
            t = 1.0f - m00 + m11 - m22;
            q0 = m01 + m10; q1 = t; q2 = m12 + m21; q3 = m20 - m02;
        }
    } else {
        if (m00 < -m11) {
            t = 1.0f - m00 - m11 + m22;
            q0 = m20 + m02; q1 = m12 + m21; q2 = t; q3 = m01 - m10;
        } else {
            t = 1.0f + m00 + m11 + m22;
            q0 = m12 - m21; q1 = m20 - m02; q2 = m01 - m10; q3 = t;
        }
    }
    float s = 0.5f / sqrtf(t);
    out7[0] = tx; out7[1] = ty; out7[2] = tz;
    out7[3] = q0 * s; out7[4] = q1 * s; out7[5] = q2 * s; out7[6] = q3 * s;
}

// =================== Kernel A: poses + key embeddings ===================
__global__ void kA(const float* __restrict__ pose_o, const float* __restrict__ pose_q,
                   const float* __restrict__ Wk1, const float* __restrict__ bk1,
                   const float* __restrict__ Wk2, const float* __restrict__ bk2,
                   float* __restrict__ out_poq, float* __restrict__ out_pqq)
{
    int t = threadIdx.x;  // 256 threads, 1 block

    // pose_o quats
    {
        float q7[7];
        mat2quat7(pose_o + t * 12, q7);
#pragma unroll
        for (int i = 0; i < 7; i++) out_poq[t * 7 + i] = q7[i];
    }
    // pose_q quats
    if (t < BB) {
        float q7[7];
        mat2quat7(pose_q + t * 12, q7);
#pragma unroll
        for (int i = 0; i < 7; i++) out_pqq[t * 7 + i] = q7[i];
    }

    // relative pose: inv([Ro|to]) @ [Rq|tq]  (fp64 adjugate inverse)
    {
        const float* po = pose_o + t * 12;
        const float* pq = pose_q + (t >> 3) * 12;
        double a[3][3], to[3], Rq[3][3], tq[3];
#pragma unroll
        for (int i = 0; i < 3; i++) {
#pragma unroll
            for (int j = 0; j < 3; j++) { a[i][j] = po[i * 4 + j]; Rq[i][j] = pq[i * 4 + j]; }
            to[i] = po[i * 4 + 3]; tq[i] = pq[i * 4 + 3];
        }
        double c00 = a[1][1] * a[2][2] - a[1][2] * a[2][1];
        double c01 = a[1][2] * a[2][0] - a[1][0] * a[2][2];
        double c02 = a[1][0] * a[2][1] - a[1][1] * a[2][0];
        double det = a[0][0] * c00 + a[0][1] * c01 + a[0][2] * c02;
        double inv[3][3];
        inv[0][0] = c00 / det;
        inv[1][0] = c01 / det;
        inv[2][0] = c02 / det;
        inv[0][1] = (a[0][2] * a[2][1] - a[0][1] * a[2][2]) / det;
        inv[1][1] = (a[0][0] * a[2][2] - a[0][2] * a[2][0]) / det;
        inv[2][1] = (a[0][1] * a[2][0] - a[0][0] * a[2][1]) / det;
        inv[0][2] = (a[0][1] * a[1][2] - a[0][2] * a[1][1]) / det;
        inv[1][2] = (a[0][2] * a[1][0] - a[0][0] * a[1][2]) / det;
        inv[2][2] = (a[0][0] * a[1][1] - a[0][1] * a[1][0]) / det;
#pragma unroll
        for (int i = 0; i < 3; i++) {
#pragma unroll
            for (int j = 0; j < 3; j++) {
                double s = 0.0;
#pragma unroll
                for (int k = 0; k < 3; k++) s += inv[i][k] * Rq[k][j];
                g_pose_trans[t * 12 + i * 4 + j] = (float)s;
            }
            double s = 0.0;
#pragma unroll
            for (int k = 0; k < 3; k++) s += inv[i][k] * (tq[k] - to[k]);
            g_pose_trans[t * 12 + i * 4 + 3] = (float)s;
        }
    }

    // key embeddings: 2 -> 128 relu -> 32, one key per thread
    {
        float c0 = lin16(t >> 4), c1 = lin16(t & 15);
        float h[128];
#pragma unroll
        for (int j = 0; j < 128; j++) {
            float v = fmaf(c0, Wk1[j], fmaf(c1, Wk1[128 + j], bk1[j]));
            h[j] = fmaxf(v, 0.0f);
        }
#pragma unroll 4
        for (int e = 0; e < EMBD; e++) {
            float s = bk2[e];
#pragma unroll
            for (int j = 0; j < 128; j++) s = fmaf(h[j], Wk2[j * EMBD + e], s);
            g_embo[t * EMBD + e] = s;
        }
    }
}

// =================== Kernel B: fused main ===================
// smem layout (float offsets)
#define OFF_WQ2T  0                         // [32][258]
#define OFF_BQ2   (OFF_WQ2T + 32*258)       // [32]
#define OFF_WA1T  (OFF_BQ2 + 32)            // [64][33]
#define OFF_WA2   (OFF_WA1T + 64*33)        // [64]
#define OFF_BA1   (OFF_WA2 + 64)            // [64]
#define OFF_EMBO  (OFF_BA1 + 64)            // [256][33]
#define OFF_EMBQ  (OFF_EMBO + 256*33)       // [64][33]
#define OFF_HID   (OFF_EMBQ + 64*33)        // [64][258]  (union: att)
#define OFF_V     (OFF_HID + 64*258)        // [128][66]  (union: a1[64][65], out-staging)
#define OFF_MASKW (OFF_V + 128*66)          // [64]
#define OFF_POSE  (OFF_MASKW + 64)          // [16]
#define OFF_CODE  (OFF_POSE + 16)           // [64][3]
#define SMEM_FLOATS (OFF_CODE + 64*3)
#define SMEM_BYTES  (SMEM_FLOATS * 4)

extern __shared__ float sm[];

__global__ void __launch_bounds__(256, 1)
kB(const float* __restrict__ vc,
   const float* __restrict__ Wq1, const float* __restrict__ bq1,
   const float* __restrict__ Wq2, const float* __restrict__ bq2,
   const float* __restrict__ Wa1, const float* __restrict__ ba1,
   const float* __restrict__ Wa2, const float* __restrict__ ba2,
   float* __restrict__ dout)
{
    const int t  = threadIdx.x;
    const int tx = t & 15;
    const int ty = t >> 4;
    const int qt = blockIdx.x;   // 0..23
    const int b  = blockIdx.y;   // 0..31

    float* sWq2T = sm + OFF_WQ2T;
    float* sbq2  = sm + OFF_BQ2;
    float* sWa1T = sm + OFF_WA1T;
    float* sWa2  = sm + OFF_WA2;
    float* sba1  = sm + OFF_BA1;
    float* sEmbO = sm + OFF_EMBO;
    float* sEmbQ = sm + OFF_EMBQ;
    float* sHid  = sm + OFF_HID;
    float* sAtt  = sm + OFF_HID;   // union
    float* sV    = sm + OFF_V;
    float* sA1   = sm + OFF_V;     // union
    float* sMW   = sm + OFF_MASKW;
    float* sPose = sm + OFF_POSE;
    float* sCode = sm + OFF_CODE;

    // ---- one-time loads ----
    for (int i = t; i < 256 * 32; i += 256) {
        int h = i >> 5, e = i & 31;
        sWq2T[e * 258 + h] = Wq2[i];
    }
    for (int i = t; i < 32 * 64; i += 256) {
        int e = i >> 6, j = i & 63;
        sWa1T[j * 33 + e] = Wa1[i];
    }
    if (t < 64) { sWa2[t] = Wa2[t]; sba1[t] = ba1[t]; }
    if (t < 32) sbq2[t] = bq2[t];
    for (int i = t; i < 256 * 32; i += 256) {
        int k = i >> 5, e = i & 31;
        sEmbO[k * 33 + e] = g_embo[i];
    }
    if (t < 64) {
        int q = qt * TQ + t;
        int d = q >> 8, rm = q & 255;
        sCode[t * 3 + 0] = 0.2f * (float)d;
        sCode[t * 3 + 1] = lin16(rm >> 4);
        sCode[t * 3 + 2] = lin16(rm & 15);
    }

    // per-thread hidden-layer weights (column t of Wq1) stay in registers
    float wq[15];
#pragma unroll
    for (int i = 0; i < 15; i++) wq[i] = Wq1[i * 256 + t];
    const float wb = bq1[t];
    const float ba2v = ba2[0];

    float acc[4][8];
#pragma unroll
    for (int i = 0; i < 4; i++)
#pragma unroll
        for (int j = 0; j < 8; j++) acc[i][j] = 0.0f;

    __syncthreads();

    for (int n = 0; n < NN; n++) {
        const int bn = b * NN + n;
        if (t < 12) sPose[t] = g_pose_trans[bn * 12 + t];
        __syncthreads();

        // ---- stage 1: hidden[64][256] = relu(inp @ Wq1 + b) ----
        {
            float base = wb;
#pragma unroll
            for (int i = 0; i < 12; i++) base = fmaf(sPose[i], wq[i], base);
#pragma unroll 4
            for (int r = 0; r < 64; r++) {
                float v = base;
                v = fmaf(sCode[r * 3 + 0], wq[12], v);
                v = fmaf(sCode[r * 3 + 1], wq[13], v);
                v = fmaf(sCode[r * 3 + 2], wq[14], v);
                sHid[r * 258 + t] = fmaxf(v, 0.0f);
            }
        }
        __syncthreads();

        // ---- stage 2: embq[64][32] = hidden @ Wq2 + b ----
        {
            const int rp = t >> 3;          // 0..31 -> rows rp*2, rp*2+1
            const int e4 = (t & 7) * 4;     // 4 consecutive emb cols
            float a0[4] = {0, 0, 0, 0}, a1[4] = {0, 0, 0, 0};
            const float* h0p = &sHid[(rp * 2) * 258];
            const float* h1p = &sHid[(rp * 2 + 1) * 258];
#pragma unroll 8
            for (int h = 0; h < 256; h += 2) {
                float2 h0 = *(const float2*)(h0p + h);
                float2 h1 = *(const float2*)(h1p + h);
#pragma unroll
                for (int j = 0; j < 4; j++) {
                    float2 w2 = *(const float2*)&sWq2T[(e4 + j) * 258 + h];
                    a0[j] = fmaf(h0.x, w2.x, a0[j]); a0[j] = fmaf(h0.y, w2.y, a0[j]);
                    a1[j] = fmaf(h1.x, w2.x, a1[j]); a1[j] = fmaf(h1.y, w2.y, a1[j]);
                }
            }
#pragma unroll
            for (int j = 0; j < 4; j++) {
                sEmbQ[(rp * 2) * 33 + e4 + j]     = a0[j] + sbq2[e4 + j];
                sEmbQ[(rp * 2 + 1) * 33 + e4 + j] = a1[j] + sbq2[e4 + j];
            }
        }
        __syncthreads();

        // ---- stage 3a: a1[64][64] = relu(embq @ Wa1 + ba1) ----
        {
            float mA[4][4];
#pragma unroll
            for (int i = 0; i < 4; i++)
#pragma unroll
                for (int j = 0; j < 4; j++) mA[i][j] = 0.0f;
#pragma unroll 4
            for (int e = 0; e < 32; e++) {
                float eq[4], wa[4];
#pragma unroll
                for (int i = 0; i < 4; i++) eq[i] = sEmbQ[(ty + 16 * i) * 33 + e];
#pragma unroll
                for (int j = 0; j < 4; j++) wa[j] = sWa1T[(tx + 16 * j) * 33 + e];
#pragma unroll
                for (int i = 0; i < 4; i++)
#pragma unroll
                    for (int j = 0; j < 4; j++) mA[i][j] = fmaf(eq[i], wa[j], mA[i][j]);
            }
#pragma unroll
            for (int i = 0; i < 4; i++)
#pragma unroll
                for (int j = 0; j < 4; j++)
                    sA1[(ty + 16 * i) * 65 + tx + 16 * j] =
                        fmaxf(mA[i][j] + sba1[tx + 16 * j], 0.0f);
        }
        __syncthreads();

        // ---- stage 3b: mask[r] = sigmoid(a1 @ Wa2 + ba2) ----
        if (t < 64) {
            float s = ba2v;
#pragma unroll 8
            for (int j = 0; j < 64; j++) s = fmaf(sA1[t * 65 + j], sWa2[j], s);
            sMW[t] = 1.0f / (1.0f + __expf(-s));
        }

        // ---- stage 4: logits[64][256] = embq @ emboT ----
#pragma unroll
        for (int p = 0; p < 2; p++) {
            float lg[4][8];
#pragma unroll
            for (int i = 0; i < 4; i++)
#pragma unroll
                for (int j = 0; j < 8; j++) lg[i][j] = 0.0f;
#pragma unroll 4
            for (int e = 0; e < 32; e++) {
                float eq[4], eo[8];
#pragma unroll
                for (int i = 0; i < 4; i++) eq[i] = sEmbQ[(ty + 16 * i) * 33 + e];
#pragma unroll
                for (int j = 0; j < 8; j++) eo[j] = sEmbO[(tx + 16 * j + 128 * p) * 33 + e];
#pragma unroll
                for (int i = 0; i < 4; i++)
#pragma unroll
                    for (int j = 0; j < 8; j++) lg[i][j] = fmaf(eq[i], eo[j], lg[i][j]);
            }
#pragma unroll
            for (int i = 0; i < 4; i++)
#pragma unroll
                for (int j = 0; j < 8; j++)
                    sAtt[(ty + 16 * i) * 258 + tx + 16 * j + 128 * p] = lg[i][j];
        }
        __syncthreads();

        // ---- stage 5: softmax rows; fold (mask/sum) into att ----
        {
            const int wid = t >> 5, lane = t & 31;
#pragma unroll
            for (int rr = 0; rr < 8; rr++) {
                const int r = wid * 8 + rr;
                float* row = &sAtt[r * 258];
                float mx = -1e30f;
#pragma unroll
                for (int k = lane; k < 256; k += 32) mx = fmaxf(mx, row[k]);
#pragma unroll
                for (int o = 16; o > 0; o >>= 1) mx = fmaxf(mx, __shfl_xor_sync(0xffffffffu, mx, o));
                float s = 0.0f;
#pragma unroll
                for (int k = lane; k < 256; k += 32) {
                    float e = __expf(row[k] - mx);
                    row[k] = e;
                    s += e;
                }
#pragma unroll
                for (int o = 16; o > 0; o >>= 1) s += __shfl_xor_sync(0xffffffffu, s, o);
                float wr = sMW[r] / s;
#pragma unroll
                for (int k = lane; k < 256; k += 32) row[k] *= wr;
            }
        }
        __syncthreads();

        // ---- stage 6: acc += att_weighted @ V^T (chunked over k) ----
        const float* vcn = vc + (size_t)bn * CELLD * KKEY;
        for (int kc = 0; kc < 4; kc++) {
            // stage V tile [128 c][64 k]
            for (int id = t; id < 2048; id += 256) {
                int c = id >> 4, f4 = id & 15;
                float4 vv = *(const float4*)(vcn + c * 256 + kc * 64 + f4 * 4);
                float* dst = &sV[c * 66 + f4 * 4];
                *(float2*)(dst)     = make_float2(vv.x, vv.y);
                *(float2*)(dst + 2) = make_float2(vv.z, vv.w);
            }
            __syncthreads();
            const int kb = kc * 64;
#pragma unroll 4
            for (int k = 0; k < 64; k += 2) {
                float2 a2[4], v2[8];
#pragma unroll
                for (int i = 0; i < 4; i++)
                    a2[i] = *(const float2*)&sAtt[(ty + 16 * i) * 258 + kb + k];
#pragma unroll
                for (int j = 0; j < 8; j++)
                    v2[j] = *(const float2*)&sV[(tx + 16 * j) * 66 + k];
#pragma unroll
                for (int i = 0; i < 4; i++)
#pragma unroll
                    for (int j = 0; j < 8; j++) {
                        acc[i][j] = fmaf(a2[i].x, v2[j].x, acc[i][j]);
                        acc[i][j] = fmaf(a2[i].y, v2[j].y, acc[i][j]);
                    }
            }
            __syncthreads();
        }
    } // n loop

    // ---- epilogue: sigmoid, transpose via smem, coalesced store ----
#pragma unroll
    for (int i = 0; i < 4; i++)
#pragma unroll
        for (int j = 0; j < 8; j++)
            sV[(tx + 16 * j) * 66 + ty + 16 * i] = 1.0f / (1.0f + __expf(-acc[i][j]));
    __syncthreads();

    float* outp = dout + (size_t)b * CELLD * QQ + qt * TQ;
    for (int id = t; id < CELLD * TQ; id += 256) {
        int c = id >> 6, r = id & 63;
        outp[(size_t)c * QQ + r] = sV[c * 66 + r];
    }
}

// =================== launch ===================
extern "C" void kernel_launch(void* const* d_in, const int* in_sizes, int n_in,
                              void* d_out, int out_size)
{
    (void)in_sizes; (void)n_in; (void)out_size;
    const float* view_cell = (const float*)d_in[0];
    const float* pose_o    = (const float*)d_in[1];
    const float* pose_q    = (const float*)d_in[2];
    const float* Wk1 = (const float*)d_in[3];
    const float* bk1 = (const float*)d_in[4];
    const float* Wk2 = (const float*)d_in[5];
    const float* bk2 = (const float*)d_in[6];
    const float* Wq1 = (const float*)d_in[7];
    const float* bq1 = (const float*)d_in[8];
    const float* Wq2 = (const float*)d_in[9];
    const float* bq2 = (const float*)d_in[10];
    const float* Wa1 = (const float*)d_in[11];
    const float* ba1 = (const float*)d_in[12];
    const float* Wa2 = (const float*)d_in[13];
    const float* ba2 = (const float*)d_in[14];

    float* out = (float*)d_out;
    float* out_poq = out + (size_t)BB * CELLD * QQ;           // [32,8,7]
    float* out_pqq = out_poq + (size_t)BB * NN * 7;           // [32,1,7]

    cudaFuncSetAttribute(kB, cudaFuncAttributeMaxDynamicSharedMemorySize, SMEM_BYTES);

    kA<<<1, 256>>>(pose_o, pose_q, Wk1, bk1, Wk2, bk2, out_poq, out_pqq);
    kB<<<dim3(24, 32), 256, SMEM_BYTES>>>(view_cell, Wq1, bq1, Wq2, bq2,
                                          Wa1, ba1, Wa2, ba2, out);
}

// round 3
// speedup vs baseline: 1.0996x; 1.0380x over previous
#include <cuda_runtime.h>
#include <math.h>

// Problem constants
#define HH    16
#define WW    16
#define DD    6
#define EMBD  32
#define CELLD 128
#define BB    32
#define NN    8
#define BND   256           // B*N
#define QQ    1536          // D*H*W
#define KKEY  256           // H*W
#define TQ    64            // q rows per block

typedef unsigned long long u64;

// packed dual-FMA: d = a*b + c elementwise on {lo,hi} fp32 pairs (sm_103a FFMA2)
#define FMA2(d, a, b, c) \
    asm("fma.rn.f32x2 %0, %1, %2, %3;" : "=l"(d) : "l"(a), "l"(b), "l"(c))

__device__ __forceinline__ float u2lo(u64 u) { return __uint_as_float((unsigned)(u & 0xffffffffu)); }
__device__ __forceinline__ float u2hi(u64 u) { return __uint_as_float((unsigned)(u >> 32)); }
__device__ __forceinline__ float u2sum(u64 u) { return u2lo(u) + u2hi(u); }

// ---- scratch (device globals; no allocations allowed) ----
__device__ float g_pose_trans[BND * 12];
__device__ float g_embo[KKEY * EMBD];

__device__ __forceinline__ float lin16(int i) { return -1.0f + (2.0f / 15.0f) * (float)i; }

__device__ __forceinline__ void mat2quat7(const float* m, float* out7) {
    float m00 = m[0], m01 = m[1], m02 = m[2], tx = m[3];
    float m10 = m[4], m11 = m[5], m12 = m[6], ty = m[7];
    float m20 = m[8], m21 = m[9], m22 = m[10], tz = m[11];
    float t, q0, q1, q2, q3;
    if (m22 < 0.0f) {
        if (m00 > m11) {
            t = 1.0f + m00 - m11 - m22;
            q0 = t; q1 = m01 + m10; q2 = m20 + m02; q3 = m12 - m21;
        } else {
            t = 1.0f - m00 + m11 - m22;
            q0 = m01 + m10; q1 = t; q2 = m12 + m21; q3 = m20 - m02;
        }
    } else {
        if (m00 < -m11) {
            t = 1.0f - m00 - m11 + m22;
            q0 = m20 + m02; q1 = m12 + m21; q2 = t; q3 = m01 - m10;
        } else {
            t = 1.0f + m00 + m11 + m22;
            q0 = m12 - m21; q1 = m20 - m02; q2 = m01 - m10; q3 = t;
        }
    }
    float s = 0.5f / sqrtf(t);
    out7[0] = tx; out7[1] = ty; out7[2] = tz;
    out7[3] = q0 * s; out7[4] = q1 * s; out7[5] = q2 * s; out7[6] = q3 * s;
}

// =================== Kernel A: poses + key embeddings ===================
__global__ void kA(const float* __restrict__ pose_o, const float* __restrict__ pose_q,
                   const float* __restrict__ Wk1, const float* __restrict__ bk1,
                   const float* __restrict__ Wk2, const float* __restrict__ bk2,
                   float* __restrict__ out_poq, float* __restrict__ out_pqq)
{
    int t = threadIdx.x;  // 256 threads, 1 block

    // pose_o quats
    {
        float q7[7];
        mat2quat7(pose_o + t * 12, q7);
#pragma unroll
        for (int i = 0; i < 7; i++) out_poq[t * 7 + i] = q7[i];
    }
    // pose_q quats
    if (t < BB) {
        float q7[7];
        mat2quat7(pose_q + t * 12, q7);
#pragma unroll
        for (int i = 0; i < 7; i++) out_pqq[t * 7 + i] = q7[i];
    }

    // relative pose: inv([Ro|to]) @ [Rq|tq]  (fp64 adjugate inverse)
    {
        const float* po = pose_o + t * 12;
        const float* pq = pose_q + (t >> 3) * 12;
        double a[3][3], to[3], Rq[3][3], tq[3];
#pragma unroll
        for (int i = 0; i < 3; i++) {
#pragma unroll
            for (int j = 0; j < 3; j++) { a[i][j] = po[i * 4 + j]; Rq[i][j] = pq[i * 4 + j]; }
            to[i] = po[i * 4 + 3]; tq[i] = pq[i * 4 + 3];
        }
        double c00 = a[1][1] * a[2][2] - a[1][2] * a[2][1];
        double c01 = a[1][2] * a[2][0] - a[1][0] * a[2][2];
        double c02 = a[1][0] * a[2][1] - a[1][1] * a[2][0];
        double det = a[0][0] * c00 + a[0][1] * c01 + a[0][2] * c02;
        double inv[3][3];
        inv[0][0] = c00 / det;
        inv[1][0] = c01 / det;
        inv[2][0] = c02 / det;
        inv[0][1] = (a[0][2] * a[2][1] - a[0][1] * a[2][2]) / det;
        inv[1][1] = (a[0][0] * a[2][2] - a[0][2] * a[2][0]) / det;
        inv[2][1] = (a[0][1] * a[2][0] - a[0][0] * a[2][1]) / det;
        inv[0][2] = (a[0][1] * a[1][2] - a[0][2] * a[1][1]) / det;
        inv[1][2] = (a[0][2] * a[1][0] - a[0][0] * a[1][2]) / det;
        inv[2][2] = (a[0][0] * a[1][1] - a[0][1] * a[1][0]) / det;
#pragma unroll
        for (int i = 0; i < 3; i++) {
#pragma unroll
            for (int j = 0; j < 3; j++) {
                double s = 0.0;
#pragma unroll
                for (int k = 0; k < 3; k++) s += inv[i][k] * Rq[k][j];
                g_pose_trans[t * 12 + i * 4 + j] = (float)s;
            }
            double s = 0.0;
#pragma unroll
            for (int k = 0; k < 3; k++) s += inv[i][k] * (tq[k] - to[k]);
            g_pose_trans[t * 12 + i * 4 + 3] = (float)s;
        }
    }

    // key embeddings: 2 -> 128 relu -> 32, one key per thread
    {
        float c0 = lin16(t >> 4), c1 = lin16(t & 15);
        float h[128];
#pragma unroll
        for (int j = 0; j < 128; j++) {
            float v = fmaf(c0, Wk1[j], fmaf(c1, Wk1[128 + j], bk1[j]));
            h[j] = fmaxf(v, 0.0f);
        }
#pragma unroll 4
        for (int e = 0; e < EMBD; e++) {
            float s = bk2[e];
#pragma unroll
            for (int j = 0; j < 128; j++) s = fmaf(h[j], Wk2[j * EMBD + e], s);
            g_embo[t * EMBD + e] = s;
        }
    }
}

// =================== Kernel B: fused main ===================
// smem layout (float offsets) — all arrays accessed as u64 keep even offsets/pitches
#define OFF_WQ2T  0                         // [32][258]
#define OFF_BQ2   (OFF_WQ2T + 32*258)       // [32]
#define OFF_WA1T  (OFF_BQ2 + 32)            // [64][34]
#define OFF_WA2   (OFF_WA1T + 64*34)        // [64]
#define OFF_BA1   (OFF_WA2 + 64)            // [64]
#define OFF_EMBO  (OFF_BA1 + 64)            // [256][34]
#define OFF_EMBQ  (OFF_EMBO + 256*34)       // [64][34]
#define OFF_HID   (OFF_EMBQ + 64*34)        // [64][258]  (union: att)
#define OFF_V     (OFF_HID + 64*258)        // [128][66]  (union: a1[64][66], out-staging)
#define OFF_MASKW (OFF_V + 128*66)          // [64]
#define OFF_POSE  (OFF_MASKW + 64)          // [16]
#define OFF_CODE  (OFF_POSE + 16)           // [64][3]
#define SMEM_FLOATS (OFF_CODE + 64*3 + 4)
#define SMEM_BYTES  (SMEM_FLOATS * 4)

extern __shared__ float sm[];

__global__ void __launch_bounds__(256, 1)
kB(const float* __restrict__ vc,
   const float* __restrict__ Wq1, const float* __restrict__ bq1,
   const float* __restrict__ Wq2, const float* __restrict__ bq2,
   const float* __restrict__ Wa1, const float* __restrict__ ba1,
   const float* __restrict__ Wa2, const float* __restrict__ ba2,
   float* __restrict__ dout)
{
    const int t  = threadIdx.x;
    const int tx = t & 15;
    const int ty = t >> 4;
    const int qt = blockIdx.x;   // 0..23
    const int b  = blockIdx.y;   // 0..31

    float* sWq2T = sm + OFF_WQ2T;
    float* sbq2  = sm + OFF_BQ2;
    float* sWa1T = sm + OFF_WA1T;
    float* sWa2  = sm + OFF_WA2;
    float* sba1  = sm + OFF_BA1;
    float* sEmbO = sm + OFF_EMBO;
    float* sEmbQ = sm + OFF_EMBQ;
    float* sHid  = sm + OFF_HID;
    float* sAtt  = sm + OFF_HID;   // union
    float* sV    = sm + OFF_V;
    float* sA1   = sm + OFF_V;     // union
    float* sMW   = sm + OFF_MASKW;
    float* sPose = sm + OFF_POSE;
    float* sCode = sm + OFF_CODE;

    // ---- one-time loads ----
    for (int i = t; i < 256 * 32; i += 256) {
        int h = i >> 5, e = i & 31;
        sWq2T[e * 258 + h] = Wq2[i];
    }
    for (int i = t; i < 32 * 64; i += 256) {
        int e = i >> 6, j = i & 63;
        sWa1T[j * 34 + e] = Wa1[i];
    }
    if (t < 64) { sWa2[t] = Wa2[t]; sba1[t] = ba1[t]; }
    if (t < 32) sbq2[t] = bq2[t];
    for (int i = t; i < 256 * 32; i += 256) {
        int k = i >> 5, e = i & 31;
        sEmbO[k * 34 + e] = g_embo[i];
    }
    if (t < 64) {
        int q = qt * TQ + t;
        int d = q >> 8, rm = q & 255;
        sCode[t * 3 + 0] = 0.2f * (float)d;
        sCode[t * 3 + 1] = lin16(rm >> 4);
        sCode[t * 3 + 2] = lin16(rm & 15);
    }

    // per-thread hidden-layer weights (column t of Wq1) stay in registers
    float wq[15];
#pragma unroll
    for (int i = 0; i < 15; i++) wq[i] = Wq1[i * 256 + t];
    const float wb = bq1[t];
    const float ba2v = ba2[0];

    // packed accumulators: {even-k, odd-k} partial sums, 4 rows x 8 cols
    u64 acc2[4][8];
#pragma unroll
    for (int i = 0; i < 4; i++)
#pragma unroll
        for (int j = 0; j < 8; j++) acc2[i][j] = 0ULL;

    __syncthreads();

    for (int n = 0; n < NN; n++) {
        const int bn = b * NN + n;
        if (t < 12) sPose[t] = g_pose_trans[bn * 12 + t];
        __syncthreads();

        // ---- stage 1: hidden[64][256] = relu(inp @ Wq1 + b) ----
        {
            float base = wb;
#pragma unroll
            for (int i = 0; i < 12; i++) base = fmaf(sPose[i], wq[i], base);
#pragma unroll 4
            for (int r = 0; r < 64; r++) {
                float v = base;
                v = fmaf(sCode[r * 3 + 0], wq[12], v);
                v = fmaf(sCode[r * 3 + 1], wq[13], v);
                v = fmaf(sCode[r * 3 + 2], wq[14], v);
                sHid[r * 258 + t] = fmaxf(v, 0.0f);
            }
        }
        __syncthreads();

        // ---- stage 2: embq[64][32] = hidden @ Wq2 + b (packed along h) ----
        {
            const int rp = t >> 3;          // 0..31 -> rows rp*2, rp*2+1
            const int e4 = (t & 7) * 4;     // 4 consecutive emb cols
            u64 a02[4] = {0, 0, 0, 0}, a12[4] = {0, 0, 0, 0};
            const u64* h0p = (const u64*)&sHid[(rp * 2) * 258];
            const u64* h1p = (const u64*)&sHid[(rp * 2 + 1) * 258];
#pragma unroll 8
            for (int h2 = 0; h2 < 128; h2++) {
                u64 h0 = h0p[h2];
                u64 h1 = h1p[h2];
#pragma unroll
                for (int j = 0; j < 4; j++) {
                    u64 w2 = *(const u64*)&sWq2T[(e4 + j) * 258 + 2 * h2];
                    FMA2(a02[j], h0, w2, a02[j]);
                    FMA2(a12[j], h1, w2, a12[j]);
                }
            }
#pragma unroll
            for (int j = 0; j < 4; j++) {
                sEmbQ[(rp * 2) * 34 + e4 + j]     = u2sum(a02[j]) + sbq2[e4 + j];
                sEmbQ[(rp * 2 + 1) * 34 + e4 + j] = u2sum(a12[j]) + sbq2[e4 + j];
            }
        }
        __syncthreads();

        // ---- stage 3a: a1[64][64] = relu(embq @ Wa1 + ba1) (packed along e) ----
        {
            u64 mA2[4][4];
#pragma unroll
            for (int i = 0; i < 4; i++)
#pragma unroll
                for (int j = 0; j < 4; j++) mA2[i][j] = 0ULL;
#pragma unroll 4
            for (int e2 = 0; e2 < 16; e2++) {
                u64 eq[4], wa[4];
#pragma unroll
                for (int i = 0; i < 4; i++) eq[i] = *(const u64*)&sEmbQ[(ty + 16 * i) * 34 + 2 * e2];
#pragma unroll
                for (int j = 0; j < 4; j++) wa[j] = *(const u64*)&sWa1T[(tx + 16 * j) * 34 + 2 * e2];
#pragma unroll
                for (int i = 0; i < 4; i++)
#pragma unroll
                    for (int j = 0; j < 4; j++) FMA2(mA2[i][j], eq[i], wa[j], mA2[i][j]);
            }
#pragma unroll
            for (int i = 0; i < 4; i++)
#pragma unroll
                for (int j = 0; j < 4; j++)
                    sA1[(ty + 16 * i) * 66 + tx + 16 * j] =
                        fmaxf(u2sum(mA2[i][j]) + sba1[tx + 16 * j], 0.0f);
        }
        __syncthreads();

        // ---- stage 3b: mask[r] = sigmoid(a1 @ Wa2 + ba2) (packed along j) ----
        if (t < 64) {
            u64 s2 = 0ULL;
            const u64* a1p = (const u64*)&sA1[t * 66];
            const u64* w2p = (const u64*)sWa2;
#pragma unroll 8
            for (int j2 = 0; j2 < 32; j2++) FMA2(s2, a1p[j2], w2p[j2], s2);
            float s = u2sum(s2) + ba2v;
            sMW[t] = 1.0f / (1.0f + __expf(-s));
        }

        // ---- stage 4: logits[64][256] = embq @ emboT (packed along e) ----
#pragma unroll
        for (int p = 0; p < 2; p++) {
            u64 lg2[4][8];
#pragma unroll
            for (int i = 0; i < 4; i++)
#pragma unroll
                for (int j = 0; j < 8; j++) lg2[i][j] = 0ULL;
#pragma unroll 4
            for (int e2 = 0; e2 < 16; e2++) {
                u64 eq[4], eo[8];
#pragma unroll
                for (int i = 0; i < 4; i++) eq[i] = *(const u64*)&sEmbQ[(ty + 16 * i) * 34 + 2 * e2];
#pragma unroll
                for (int j = 0; j < 8; j++) eo[j] = *(const u64*)&sEmbO[(tx + 16 * j + 128 * p) * 34 + 2 * e2];
#pragma unroll
                for (int i = 0; i < 4; i++)
#pragma unroll
                    for (int j = 0; j < 8; j++) FMA2(lg2[i][j], eq[i], eo[j], lg2[i][j]);
            }
#pragma unroll
            for (int i = 0; i < 4; i++)
#pragma unroll
                for (int j = 0; j < 8; j++)
                    sAtt[(ty + 16 * i) * 258 + tx + 16 * j + 128 * p] = u2sum(lg2[i][j]);
        }
        __syncthreads();

        // ---- stage 5: softmax rows; fold (mask/sum) into att ----
        {
            const int wid = t >> 5, lane = t & 31;
#pragma unroll
            for (int rr = 0; rr < 8; rr++) {
                const int r = wid * 8 + rr;
                float* row = &sAtt[r * 258];
                float mx = -1e30f;
#pragma unroll
                for (int k = lane; k < 256; k += 32) mx = fmaxf(mx, row[k]);
#pragma unroll
                for (int o = 16; o > 0; o >>= 1) mx = fmaxf(mx, __shfl_xor_sync(0xffffffffu, mx, o));
                float s = 0.0f;
#pragma unroll
                for (int k = lane; k < 256; k += 32) {
                    float e = __expf(row[k] - mx);
                    row[k] = e;
                    s += e;
                }
#pragma unroll
                for (int o = 16; o > 0; o >>= 1) s += __shfl_xor_sync(0xffffffffu, s, o);
                float wr = sMW[r] / s;
#pragma unroll
                for (int k = lane; k < 256; k += 32) row[k] *= wr;
            }
        }
        __syncthreads();

        // ---- stage 6: acc += att_weighted @ V^T (packed along k, chunked) ----
        const float* vcn = vc + (size_t)bn * CELLD * KKEY;
        for (int kc = 0; kc < 4; kc++) {
            // stage V tile [128 c][64 k]
            for (int id = t; id < 2048; id += 256) {
                int c = id >> 4, f4 = id & 15;
                float4 vv = *(const float4*)(vcn + c * 256 + kc * 64 + f4 * 4);
                float* dst = &sV[c * 66 + f4 * 4];
                *(float2*)(dst)     = make_float2(vv.x, vv.y);
                *(float2*)(dst + 2) = make_float2(vv.z, vv.w);
            }
            __syncthreads();
            const int kb = kc * 64;
#pragma unroll 4
            for (int k2 = 0; k2 < 32; k2++) {
                u64 a2[4], v2[8];
#pragma unroll
                for (int i = 0; i < 4; i++)
                    a2[i] = *(const u64*)&sAtt[(ty + 16 * i) * 258 + kb + 2 * k2];
#pragma unroll
                for (int j = 0; j < 8; j++)
                    v2[j] = *(const u64*)&sV[(tx + 16 * j) * 66 + 2 * k2];
#pragma unroll
                for (int i = 0; i < 4; i++)
#pragma unroll
                    for (int j = 0; j < 8; j++)
                        FMA2(acc2[i][j], a2[i], v2[j], acc2[i][j]);
            }
            __syncthreads();
        }
    } // n loop

    // ---- epilogue: sigmoid, transpose via smem, coalesced store ----
#pragma unroll
    for (int i = 0; i < 4; i++)
#pragma unroll
        for (int j = 0; j < 8; j++) {
            float a = u2sum(acc2[i][j]);
            sV[(tx + 16 * j) * 66 + ty + 16 * i] = 1.0f / (1.0f + __expf(-a));
        }
    __syncthreads();

    float* outp = dout + (size_t)b * CELLD * QQ + qt * TQ;
    for (int id = t; id < CELLD * TQ; id += 256) {
        int c = id >> 6, r = id & 63;
        outp[(size_t)c * QQ + r] = sV[c * 66 + r];
    }
}

// =================== launch ===================
extern "C" void kernel_launch(void* const* d_in, const int* in_sizes, int n_in,
                              void* d_out, int out_size)
{
    (void)in_sizes; (void)n_in; (void)out_size;
    const float* view_cell = (const float*)d_in[0];
    const float* pose_o    = (const float*)d_in[1];
    const float* pose_q    = (const float*)d_in[2];
    const float* Wk1 = (const float*)d_in[3];
    const float* bk1 = (const float*)d_in[4];
    const float* Wk2 = (const float*)d_in[5];
    const float* bk2 = (const float*)d_in[6];
    const float* Wq1 = (const float*)d_in[7];
    const float* bq1 = (const float*)d_in[8];
    const float* Wq2 = (const float*)d_in[9];
    const float* bq2 = (const float*)d_in[10];
    const float* Wa1 = (const float*)d_in[11];
    const float* ba1 = (const float*)d_in[12];
    const float* Wa2 = (const float*)d_in[13];
    const float* ba2 = (const float*)d_in[14];

    float* out = (float*)d_out;
    float* out_poq = out + (size_t)BB * CELLD * QQ;           // [32,8,7]
    float* out_pqq = out_poq + (size_t)BB * NN * 7;           // [32,1,7]

    cudaFuncSetAttribute(kB, cudaFuncAttributeMaxDynamicSharedMemorySize, SMEM_BYTES);

    kA<<<1, 256>>>(pose_o, pose_q, Wk1, bk1, Wk2, bk2, out_poq, out_pqq);
    kB<<<dim3(24, 32), 256, SMEM_BYTES>>>(view_cell, Wq1, bq1, Wq2, bq2,
                                          Wa1, ba1, Wa2, ba2, out);
}